// round 8
// baseline (speedup 1.0000x reference)
#include <cuda_runtime.h>
#include <cuda_bf16.h>
#include <math_constants.h>
#include <cstdint>

// Problem constants
#define NLAG   12
#define NB     32
#define NN     1200
#define MROWS  1152          // 3 * NLAG * NB (rows interleaved as triples)
#define KDIM   1200
#define KP     1216          // K padded to 38*32
#define NP     1280          // B storage width (padded)

// GEMM tiling: CTA 96m x 80n, BK=32, 384 threads (12 warps = 6m x 2n, 16x40)
#define BK      32
#define NCHUNK  (KP / BK)    // 38
#define AROWB   80
#define BROWB   176
#define A_TILE  (96 * AROWB)     // 7680
#define B_TILE  (32 * BROWB)     // 5632
#define OFF_A0  0
#define OFF_A1  A_TILE
#define OFF_B0  (2 * A_TILE)
#define OFF_B1  (2 * A_TILE + B_TILE)
#define STAGE   (2 * A_TILE + 2 * B_TILE)   // 26624
#define NUNITS  1408         // 16B units per chunk: B 2*320 + A 2*384
#define CPITCH  84           // output-staging tile pitch (floats)

// Scratch (device globals; no allocation allowed)
__device__ __align__(16) __nv_bfloat16 g_A0[MROWS * KP];
__device__ __align__(16) __nv_bfloat16 g_A1[MROWS * KP];
__device__ __align__(16) __nv_bfloat16 g_B0[KP * NP];    // k-major
__device__ __align__(16) __nv_bfloat16 g_B1[KP * NP];
__device__ float g_belta[NLAG];
__device__ float g_c2[NLAG];
__device__ float g_pf[NLAG];

// ---------------------------------------------------------------------------
__device__ __forceinline__ uint32_t smem_u32(const void* p) {
    uint32_t a;
    asm("{ .reg .u64 t; cvta.to.shared.u64 t, %1; cvt.u32.u64 %0, t; }"
        : "=r"(a) : "l"(p));
    return a;
}

#define LDSM4(r, addr)                                                      \
    asm volatile("ldmatrix.sync.aligned.m8n8.x4.shared.b16 "                \
                 "{%0, %1, %2, %3}, [%4];"                                  \
                 : "=r"((r)[0]), "=r"((r)[1]), "=r"((r)[2]), "=r"((r)[3])   \
                 : "r"(addr))
#define LDSM4T(r, addr)                                                     \
    asm volatile("ldmatrix.sync.aligned.m8n8.x4.trans.shared.b16 "          \
                 "{%0, %1, %2, %3}, [%4];"                                  \
                 : "=r"((r)[0]), "=r"((r)[1]), "=r"((r)[2]), "=r"((r)[3])   \
                 : "r"(addr))
#define LDSM2T(r, addr)                                                     \
    asm volatile("ldmatrix.sync.aligned.m8n8.x2.trans.shared.b16 "          \
                 "{%0, %1}, [%2];"                                          \
                 : "=r"((r)[0]), "=r"((r)[1]) : "r"(addr))

#define MMA_BF16(c, a, bb0, bb1)                                            \
    asm volatile("mma.sync.aligned.m16n8k16.row.col.f32.bf16.bf16.f32 "     \
                 "{%0, %1, %2, %3}, {%4, %5, %6, %7}, {%8, %9}, "           \
                 "{%0, %1, %2, %3};"                                        \
                 : "+f"((c)[0]), "+f"((c)[1]), "+f"((c)[2]), "+f"((c)[3])   \
                 : "r"((a)[0]), "r"((a)[1]), "r"((a)[2]), "r"((a)[3]),      \
                   "r"(bb0), "r"(bb1))

#define CP_ASYNC16(dst, src)                                                \
    asm volatile("cp.async.cg.shared.global [%0], [%1], 16;"                \
                 :: "r"(dst), "l"(__cvta_generic_to_global(src)))
#define CP_COMMIT() asm volatile("cp.async.commit_group;" ::: "memory")
#define CP_WAIT1()  asm volatile("cp.async.wait_group 1;" ::: "memory")
#define CP_WAIT0()  asm volatile("cp.async.wait_group 0;" ::: "memory")

// ---------------------------------------------------------------------------
__device__ __forceinline__ float gamma_fn(float x) {
    if (x > 0.f) return expf(lgammaf(x));
    return CUDART_PI_F / (sinf(CUDART_PI_F * x) * expf(lgammaf(1.f - x)));
}

// ---------------------------------------------------------------------------
// Fused prep. A rows interleaved as triples: row' = 3t+s,
//   t = lag*32 + b;  s=0: A slice, s=1: A_0_NEW, s=2: A_N_OLD.
// Ranges:
//  [0, R0)        : A slice (s=0), contiguous split copy (incl. k padding)
//  [R0, +R1)      : train_init gather, one thread per (b,i), coalesced read
//  [.., +R2)      : zero-fill k padding for s=1,2 rows
//  [.., +R3)      : B pack (k-major split)
// ---------------------------------------------------------------------------
#define R0 (384 * KP)
#define R1 (NB * NN)
#define R2 (768 * (KP - KDIM))
#define R3 (KP * (NP / 2))
#define PREP_TOTAL (R0 + R1 + R2 + R3)

__global__ void prep_kernel(const float* __restrict__ A,
                            const float* __restrict__ WW,
                            const float* __restrict__ train_init,
                            const float* __restrict__ alpha,
                            const float* __restrict__ fract) {
    int idx = blockIdx.x * blockDim.x + threadIdx.x;

    if (blockIdx.x == 0 && threadIdx.x < NLAG) {
        int lag = threadIdx.x;
        float a   = alpha[lag];
        float f   = fract[lag];
        float ga1 = gamma_fn(a + 1.f);
        float gm2 = gamma_fn(a - 2.f);
        float belta = 1.f
                    + ga1 / gamma_fn(a)
                    + ga1 / (2.f * gamma_fn(a - 1.f))
                    + ga1 / (6.f * gm2);
        g_belta[lag] = belta;
        g_c2[lag]    = ga1 / (6.f * gm2);
        g_pf[lag]    = 2.f * powf(3.f, f);
    }

    if (idx < R0) {
        int r = idx / KP;
        int k = idx - r * KP;
        float v = (k < KDIM) ? A[r * KDIM + k] : 0.f;
        __nv_bfloat16 hi = __float2bfloat16(v);
        __nv_bfloat16 lo = __float2bfloat16(v - __bfloat162float(hi));
        size_t dst = (size_t)(3 * r) * KP + k;
        g_A0[dst] = hi;
        g_A1[dst] = lo;
    } else if (idx < R0 + R1) {
        int p = idx - R0;
        int b = p / NN;
        int i = p - b * NN;
        const float2* ti = reinterpret_cast<const float2*>(
            train_init + (size_t)(b * NN + i) * 26);
#pragma unroll
        for (int j = 0; j < 13; j++) {
            float v = ti[j].y;
            __nv_bfloat16 hi = __float2bfloat16(v);
            __nv_bfloat16 lo = __float2bfloat16(v - __bfloat162float(hi));
            if (j >= 1) {               // A_0_NEW: lag = j-1, s=1
                int row = 3 * ((j - 1) * NB + b) + 1;
                g_A0[(size_t)row * KP + i] = hi;
                g_A1[(size_t)row * KP + i] = lo;
            }
            if (j <= 11) {              // A_N_OLD: lag = j, s=2
                int row = 3 * (j * NB + b) + 2;
                g_A0[(size_t)row * KP + i] = hi;
                g_A1[(size_t)row * KP + i] = lo;
            }
        }
    } else if (idx < R0 + R1 + R2) {
        int p = idx - R0 - R1;
        int which = p / (KP - KDIM);        // 0..767
        int k     = KDIM + p % (KP - KDIM);
        int row   = 3 * (which >> 1) + 1 + (which & 1);
        g_A0[(size_t)row * KP + k] = __float2bfloat16(0.f);
        g_A1[(size_t)row * KP + k] = __float2bfloat16(0.f);
    } else if (idx < PREP_TOTAL) {
        int p = idx - R0 - R1 - R2;
        int k = p / (NP / 2);
        int n = (p - k * (NP / 2)) * 2;
        float v0 = 0.f, v1 = 0.f;
        if (k < KDIM && n + 1 < NN) {
            float2 w = *reinterpret_cast<const float2*>(&WW[k * NN + n]);
            v0 = w.x; v1 = w.y;
        } else if (k < KDIM && n < NN) {
            v0 = WW[k * NN + n];
        }
        __nv_bfloat16 h0 = __float2bfloat16(v0);
        __nv_bfloat16 l0 = __float2bfloat16(v0 - __bfloat162float(h0));
        __nv_bfloat16 h1 = __float2bfloat16(v1);
        __nv_bfloat16 l1 = __float2bfloat16(v1 - __bfloat162float(h1));
        reinterpret_cast<__nv_bfloat162*>(g_B0)[p] = __halves2bfloat162(h0, h1);
        reinterpret_cast<__nv_bfloat162*>(g_B1)[p] = __halves2bfloat162(l0, l1);
    }
}

// ---------------------------------------------------------------------------
// cp.async issue for one chunk: B0,B1 32x160B; A0,A1 96x64B
// ---------------------------------------------------------------------------
__device__ __forceinline__ void issue_chunk(uint32_t stage, int m0, int n0,
                                            int k0, int tid) {
#pragma unroll
    for (int i = 0; i < 4; i++) {
        int u = tid + i * 384;
        if (u < NUNITS) {
            uint32_t dst;
            const __nv_bfloat16* src;
            if (u < 640) {                  // B tiles: 2 x 320 units
                int t   = u >= 320;
                int v   = u - t * 320;
                int row = v / 10;
                int seg = v - row * 10;
                const __nv_bfloat16* g = t ? g_B1 : g_B0;
                src = g + (size_t)(k0 + row) * NP + n0 + seg * 8;
                dst = stage + OFF_B0 + t * B_TILE + row * BROWB + seg * 16;
            } else {                        // A tiles: 2 x 384 units (96 rows)
                int u2  = u - 640;
                int t   = u2 >= 384;
                int v   = u2 - t * 384;
                int row = v >> 2;
                int seg = v & 3;
                const __nv_bfloat16* g = t ? g_A1 : g_A0;
                src = g + (size_t)(m0 + row) * KP + k0 + seg * 8;
                dst = stage + OFF_A0 + t * A_TILE + row * AROWB + seg * 16;
            }
            CP_ASYNC16(dst, src);
        }
    }
}

// ---------------------------------------------------------------------------
// Split-bf16 HMMA GEMM with FUSED final combine.
// CTA 96x80, 12 warps (16m x 40n), BK=32 double-buffered (R6 loop shape).
// Grid (15, 12); rows are (t, s)-triples so each CTA owns whole outputs.
// ---------------------------------------------------------------------------
__global__ __launch_bounds__(384, 2)
void gemm_mma_kernel(const float* __restrict__ lambd,
                     const float* __restrict__ l,
                     float* __restrict__ out) {
    extern __shared__ __align__(16) char smem[];
    const uint32_t sb = smem_u32(smem);
    const int tid  = threadIdx.x;
    const int lane = tid & 31;
    const int wid  = tid >> 5;
    const int wm   = wid % 6;        // 0..5 -> m offset wm*16
    const int wn   = wid / 6;        // 0..1 -> n offset wn*40
    const int m0   = blockIdx.y * 96;
    const int n0   = blockIdx.x * 80;

    const int j = lane >> 3, rr = lane & 7;
    const uint32_t a_off  = (uint32_t)((wm * 16 + (j & 1) * 8 + rr) * AROWB + (j >> 1) * 16);
    const uint32_t b4_off = (uint32_t)(((j & 1) * 8 + rr) * BROWB + (j >> 1) * 16 + wn * 80);
    const uint32_t b2_off = (uint32_t)(((j & 1) * 8 + rr) * BROWB + wn * 80 + 64);

    float acc[5][4];
#pragma unroll
    for (int f = 0; f < 5; f++)
#pragma unroll
        for (int e = 0; e < 4; e++) acc[f][e] = 0.f;

    issue_chunk(sb, m0, n0, 0, tid);
    CP_COMMIT();

    for (int c = 0; c < NCHUNK; c++) {
        const uint32_t stage = sb + (uint32_t)(c & 1) * STAGE;
        if (c + 1 < NCHUNK) {
            issue_chunk(sb + (uint32_t)((c + 1) & 1) * STAGE, m0, n0,
                        (c + 1) * BK, tid);
            CP_COMMIT();
            CP_WAIT1();
        } else {
            CP_WAIT0();
        }
        __syncthreads();

#pragma unroll
        for (int ks = 0; ks < 2; ks++) {
            uint32_t A0f[4], A1f[4];
            LDSM4(A0f, stage + OFF_A0 + a_off + ks * 32);
            LDSM4(A1f, stage + OFF_A1 + a_off + ks * 32);
            uint32_t B0r[10], B1r[10];
#pragma unroll
            for (int f = 0; f < 2; f++) {
                LDSM4T(&B0r[4 * f], stage + OFF_B0 + b4_off + f * 32 + ks * 16 * BROWB);
                LDSM4T(&B1r[4 * f], stage + OFF_B1 + b4_off + f * 32 + ks * 16 * BROWB);
            }
            LDSM2T(&B0r[8], stage + OFF_B0 + b2_off + ks * 16 * BROWB);
            LDSM2T(&B1r[8], stage + OFF_B1 + b2_off + ks * 16 * BROWB);
#pragma unroll
            for (int f = 0; f < 5; f++) {
                MMA_BF16(acc[f], A0f, B0r[2 * f], B0r[2 * f + 1]);
                MMA_BF16(acc[f], A0f, B1r[2 * f], B1r[2 * f + 1]);
                MMA_BF16(acc[f], A1f, B0r[2 * f], B0r[2 * f + 1]);
            }
        }
        __syncthreads();
    }

    // --- Fused combine ------------------------------------------------------
    // Stage tanh(-acc) tile [96][80] in smem (reuses pipeline buffers; all
    // warps passed the final __syncthreads so LDSM reads are done).
    float* ctile = reinterpret_cast<float*>(smem);
    const int gid = lane >> 2, tig = lane & 3;
    {
        const int r0 = wm * 16 + gid;
#pragma unroll
        for (int f = 0; f < 5; f++) {
            const int cc = wn * 40 + f * 8 + tig * 2;
            ctile[(r0)     * CPITCH + cc]     = tanhf(-acc[f][0]);
            ctile[(r0)     * CPITCH + cc + 1] = tanhf(-acc[f][1]);
            ctile[(r0 + 8) * CPITCH + cc]     = tanhf(-acc[f][2]);
            ctile[(r0 + 8) * CPITCH + cc + 1] = tanhf(-acc[f][3]);
        }
    }
    __syncthreads();

    // Combine triples: out[b,lag,j] = lambd/belta * (pf*OUT + 3*l*(A0 + c2*AN))
    const int t0 = blockIdx.y * 32;     // 32 triples per CTA
#pragma unroll
    for (int o = tid; o < 32 * 80; o += 384) {
        int u  = o / 80;
        int jj = o - u * 80;
        float vO = ctile[(3 * u)     * CPITCH + jj];
        float vA = ctile[(3 * u + 1) * CPITCH + jj];
        float vN = ctile[(3 * u + 2) * CPITCH + jj];
        int t   = t0 + u;
        int lag = t >> 5;
        int b   = t & 31;
        int jcol = n0 + jj;
        int jm   = jcol % 200;
        float r = lambd[lag * 200 + jm] / g_belta[lag] *
                  (g_pf[lag] * vO + 3.f * l[lag * 200 + jm] * (vA + g_c2[lag] * vN));
        out[((size_t)b * NLAG + lag) * NN + jcol] = r;
    }
}

// ---------------------------------------------------------------------------
extern "C" void kernel_launch(void* const* d_in, const int* in_sizes, int n_in,
                              void* d_out, int out_size) {
    const float* A          = (const float*)d_in[0];
    const float* WW         = (const float*)d_in[1];
    const float* train_init = (const float*)d_in[2];
    const float* alpha      = (const float*)d_in[3];
    const float* fract      = (const float*)d_in[4];
    const float* lambd      = (const float*)d_in[5];
    const float* l          = (const float*)d_in[6];
    float* out = (float*)d_out;

    cudaFuncSetAttribute(gemm_mma_kernel,
                         cudaFuncAttributeMaxDynamicSharedMemorySize,
                         2 * STAGE);

    prep_kernel<<<(PREP_TOTAL + 255) / 256, 256>>>(A, WW, train_init, alpha, fract);

    dim3 ggrid(NN / 80, MROWS / 96);              // (15, 12) = 180 CTAs
    gemm_mma_kernel<<<ggrid, 384, 2 * STAGE>>>(lambd, l, out);
}

// round 9
// speedup vs baseline: 1.6499x; 1.6499x over previous
#include <cuda_runtime.h>
#include <cuda_fp16.h>
#include <math_constants.h>
#include <cstdint>

// Problem constants
#define NLAG   12
#define NB     32
#define NN     1200
#define MROWS  1152          // 3 * NLAG * NB
#define KDIM   1200
#define KP     1216          // K padded to 38*32
#define NP     1280          // B storage width (padded)

// GEMM tiling: CTA 64m x 80n, BK=32, 256 threads (8 warps = 4m x 2n, 16x40)
#define BK      32
#define NCHUNK  (KP / BK)    // 38
#define AROWB   80
#define BROWB   176
#define A_TILE  (64 * AROWB)     // 5120
#define B_TILE  (32 * BROWB)     // 5632
#define OFF_A0  0
#define OFF_B0  A_TILE
#define OFF_B1  (A_TILE + B_TILE)
#define STAGE   (A_TILE + 2 * B_TILE)   // 16384
#define NUNITS  896          // 16B units per chunk: B 2*320 + A 256

// Scratch (device globals; no allocation allowed)
__device__ __align__(16) __half g_A0[MROWS * KP];
__device__ __align__(16) __half g_B0[KP * NP];    // k-major
__device__ __align__(16) __half g_B1[KP * NP];
__device__ __align__(16) float g_C[MROWS * NN];
__device__ float g_belta[NLAG];
__device__ float g_c2[NLAG];
__device__ float g_pf[NLAG];

// ---------------------------------------------------------------------------
__device__ __forceinline__ uint32_t smem_u32(const void* p) {
    uint32_t a;
    asm("{ .reg .u64 t; cvta.to.shared.u64 t, %1; cvt.u32.u64 %0, t; }"
        : "=r"(a) : "l"(p));
    return a;
}

#define LDSM4(r, addr)                                                      \
    asm volatile("ldmatrix.sync.aligned.m8n8.x4.shared.b16 "                \
                 "{%0, %1, %2, %3}, [%4];"                                  \
                 : "=r"((r)[0]), "=r"((r)[1]), "=r"((r)[2]), "=r"((r)[3])   \
                 : "r"(addr))
#define LDSM4T(r, addr)                                                     \
    asm volatile("ldmatrix.sync.aligned.m8n8.x4.trans.shared.b16 "          \
                 "{%0, %1, %2, %3}, [%4];"                                  \
                 : "=r"((r)[0]), "=r"((r)[1]), "=r"((r)[2]), "=r"((r)[3])   \
                 : "r"(addr))
#define LDSM2T(r, addr)                                                     \
    asm volatile("ldmatrix.sync.aligned.m8n8.x2.trans.shared.b16 "          \
                 "{%0, %1}, [%2];"                                          \
                 : "=r"((r)[0]), "=r"((r)[1]) : "r"(addr))

#define MMA_F16(c, a, bb0, bb1)                                             \
    asm volatile("mma.sync.aligned.m16n8k16.row.col.f32.f16.f16.f32 "       \
                 "{%0, %1, %2, %3}, {%4, %5, %6, %7}, {%8, %9}, "           \
                 "{%0, %1, %2, %3};"                                        \
                 : "+f"((c)[0]), "+f"((c)[1]), "+f"((c)[2]), "+f"((c)[3])   \
                 : "r"((a)[0]), "r"((a)[1]), "r"((a)[2]), "r"((a)[3]),      \
                   "r"(bb0), "r"(bb1))

#define CP_ASYNC16(dst, src)                                                \
    asm volatile("cp.async.cg.shared.global [%0], [%1], 16;"                \
                 :: "r"(dst), "l"(__cvta_generic_to_global(src)))
#define CP_COMMIT() asm volatile("cp.async.commit_group;" ::: "memory")
#define CP_WAIT1()  asm volatile("cp.async.wait_group 1;" ::: "memory")
#define CP_WAIT0()  asm volatile("cp.async.wait_group 0;" ::: "memory")

// ---------------------------------------------------------------------------
__device__ __forceinline__ float gamma_fn(float x) {
    if (x > 0.f) return expf(lgammaf(x));
    return CUDART_PI_F / (sinf(CUDART_PI_F * x) * expf(lgammaf(1.f - x)));
}

// ---------------------------------------------------------------------------
// Fused prep. A rows: [0,384) A slice, [384,768) A_0_NEW, [768,1152) A_N_OLD.
//  [0, R0)   : A slice fp16 copy (incl. k padding)
//  [R0,+R1)  : train_init gather, one thread per (b,i), coalesced read
//  [..,+R2)  : zero-fill k padding for rows [384,1152)
//  [..,+R3)  : B pack (k-major fp16 split)
// ---------------------------------------------------------------------------
#define R0 (384 * KP)
#define R1 (NB * NN)
#define R2 (768 * (KP - KDIM))
#define R3 (KP * (NP / 2))
#define PREP_TOTAL (R0 + R1 + R2 + R3)

__global__ void prep_kernel(const float* __restrict__ A,
                            const float* __restrict__ WW,
                            const float* __restrict__ train_init,
                            const float* __restrict__ alpha,
                            const float* __restrict__ fract) {
    int idx = blockIdx.x * blockDim.x + threadIdx.x;

    if (blockIdx.x == 0 && threadIdx.x < NLAG) {
        int lag = threadIdx.x;
        float a   = alpha[lag];
        float f   = fract[lag];
        float ga1 = gamma_fn(a + 1.f);
        float gm2 = gamma_fn(a - 2.f);
        float belta = 1.f
                    + ga1 / gamma_fn(a)
                    + ga1 / (2.f * gamma_fn(a - 1.f))
                    + ga1 / (6.f * gm2);
        g_belta[lag] = belta;
        g_c2[lag]    = ga1 / (6.f * gm2);
        g_pf[lag]    = 2.f * powf(3.f, f);
    }

    if (idx < R0) {
        int r = idx / KP;
        int k = idx - r * KP;
        float v = (k < KDIM) ? A[r * KDIM + k] : 0.f;
        g_A0[idx] = __float2half(v);
    } else if (idx < R0 + R1) {
        int p = idx - R0;
        int b = p / NN;
        int i = p - b * NN;
        const float2* ti = reinterpret_cast<const float2*>(
            train_init + (size_t)(b * NN + i) * 26);
#pragma unroll
        for (int j = 0; j < 13; j++) {
            __half h = __float2half(ti[j].y);
            if (j >= 1) {               // A_0_NEW: lag = j-1
                int row = 384 + (j - 1) * NB + b;
                g_A0[(size_t)row * KP + i] = h;
            }
            if (j <= 11) {              // A_N_OLD: lag = j
                int row = 768 + j * NB + b;
                g_A0[(size_t)row * KP + i] = h;
            }
        }
    } else if (idx < R0 + R1 + R2) {
        int p = idx - R0 - R1;
        int row = 384 + p / (KP - KDIM);
        int k   = KDIM + p % (KP - KDIM);
        g_A0[(size_t)row * KP + k] = __float2half(0.f);
    } else if (idx < PREP_TOTAL) {
        int p = idx - R0 - R1 - R2;
        int k = p / (NP / 2);
        int n = (p - k * (NP / 2)) * 2;
        float v0 = 0.f, v1 = 0.f;
        if (k < KDIM && n + 1 < NN) {
            float2 w = *reinterpret_cast<const float2*>(&WW[k * NN + n]);
            v0 = w.x; v1 = w.y;
        } else if (k < KDIM && n < NN) {
            v0 = WW[k * NN + n];
        }
        __half h0 = __float2half(v0);
        __half l0 = __float2half(v0 - __half2float(h0));
        __half h1 = __float2half(v1);
        __half l1 = __float2half(v1 - __half2float(h1));
        reinterpret_cast<__half2*>(g_B0)[p] = __halves2half2(h0, h1);
        reinterpret_cast<__half2*>(g_B1)[p] = __halves2half2(l0, l1);
    }
}

// ---------------------------------------------------------------------------
// cp.async issue for one chunk: B0,B1 32x160B; A0 64x64B  (896 units)
// ---------------------------------------------------------------------------
__device__ __forceinline__ void issue_chunk(uint32_t stage, int m0, int n0,
                                            int k0, int tid) {
#pragma unroll
    for (int i = 0; i < 4; i++) {
        int u = tid + i * 256;
        if (u < NUNITS) {
            uint32_t dst;
            const __half* src;
            if (u < 640) {                  // B tiles: 2 x 320 units
                int t   = u >= 320;
                int v   = u - t * 320;
                int row = v / 10;
                int seg = v - row * 10;
                const __half* g = t ? g_B1 : g_B0;
                src = g + (size_t)(k0 + row) * NP + n0 + seg * 8;
                dst = stage + OFF_B0 + t * B_TILE + row * BROWB + seg * 16;
            } else {                        // A0 tile: 256 units (64 rows)
                int v   = u - 640;
                int row = v >> 2;
                int seg = v & 3;
                src = g_A0 + (size_t)(m0 + row) * KP + k0 + seg * 8;
                dst = stage + OFF_A0 + row * AROWB + seg * 16;
            }
            CP_ASYNC16(dst, src);
        }
    }
}

// ---------------------------------------------------------------------------
// fp16 2-term HMMA GEMM: g_C = tanh(-(X @ WW)), C = A0*B0 + A0*B1.
// CTA 64x80, 8 warps (16m x 40n each), BK=32 double-buffered (R6 loop).
// Grid (15, 18) = 270 CTAs.
// ---------------------------------------------------------------------------
__global__ __launch_bounds__(256, 3)
void gemm_mma_kernel() {
    extern __shared__ __align__(16) char smem[];
    const uint32_t sb = smem_u32(smem);
    const int tid  = threadIdx.x;
    const int lane = tid & 31;
    const int wid  = tid >> 5;
    const int wm   = wid & 3;
    const int wn   = wid >> 2;
    const int m0   = blockIdx.y * 64;
    const int n0   = blockIdx.x * 80;

    const int j = lane >> 3, rr = lane & 7;
    const uint32_t a_off  = (uint32_t)((wm * 16 + (j & 1) * 8 + rr) * AROWB + (j >> 1) * 16);
    const uint32_t b4_off = (uint32_t)(((j & 1) * 8 + rr) * BROWB + (j >> 1) * 16 + wn * 80);
    const uint32_t b2_off = (uint32_t)(((j & 1) * 8 + rr) * BROWB + wn * 80 + 64);

    float acc[5][4];
#pragma unroll
    for (int f = 0; f < 5; f++)
#pragma unroll
        for (int e = 0; e < 4; e++) acc[f][e] = 0.f;

    issue_chunk(sb, m0, n0, 0, tid);
    CP_COMMIT();

    for (int c = 0; c < NCHUNK; c++) {
        const uint32_t stage = sb + (uint32_t)(c & 1) * STAGE;
        if (c + 1 < NCHUNK) {
            issue_chunk(sb + (uint32_t)((c + 1) & 1) * STAGE, m0, n0,
                        (c + 1) * BK, tid);
            CP_COMMIT();
            CP_WAIT1();
        } else {
            CP_WAIT0();
        }
        __syncthreads();

#pragma unroll
        for (int ks = 0; ks < 2; ks++) {
            uint32_t A0f[4];
            LDSM4(A0f, stage + OFF_A0 + a_off + ks * 32);
            uint32_t B0r[10], B1r[10];
#pragma unroll
            for (int f = 0; f < 2; f++) {
                LDSM4T(&B0r[4 * f], stage + OFF_B0 + b4_off + f * 32 + ks * 16 * BROWB);
                LDSM4T(&B1r[4 * f], stage + OFF_B1 + b4_off + f * 32 + ks * 16 * BROWB);
            }
            LDSM2T(&B0r[8], stage + OFF_B0 + b2_off + ks * 16 * BROWB);
            LDSM2T(&B1r[8], stage + OFF_B1 + b2_off + ks * 16 * BROWB);
#pragma unroll
            for (int f = 0; f < 5; f++) {
                MMA_F16(acc[f], A0f, B0r[2 * f], B0r[2 * f + 1]);
                MMA_F16(acc[f], A0f, B1r[2 * f], B1r[2 * f + 1]);
            }
        }
        __syncthreads();
    }

    // Store with fused tanh(-x); cols always < 1200 (grid.x*80 == NN).
    const int gid = lane >> 2, tig = lane & 3;
    const int row = m0 + wm * 16 + gid;
    float* c0p = &g_C[(size_t)row * NN];
    float* c1p = &g_C[(size_t)(row + 8) * NN];
#pragma unroll
    for (int f = 0; f < 5; f++) {
        int col = n0 + wn * 40 + f * 8 + tig * 2;
        float2 lo, hi;
        lo.x = tanhf(-acc[f][0]);
        lo.y = tanhf(-acc[f][1]);
        hi.x = tanhf(-acc[f][2]);
        hi.y = tanhf(-acc[f][3]);
        *reinterpret_cast<float2*>(c0p + col) = lo;
        *reinterpret_cast<float2*>(c1p + col) = hi;
    }
}

// ---------------------------------------------------------------------------
// Final combine (float4): out = lambd/belta * ( pf*OUT + 3*l*(A0NEW + c2*ANOLD) )
// ---------------------------------------------------------------------------
__global__ void epilogue_kernel(const float* __restrict__ lambd,
                                const float* __restrict__ l,
                                float* __restrict__ out) {
    int idx = blockIdx.x * blockDim.x + threadIdx.x;
    const int total4 = NB * NLAG * (NN / 4);
    if (idx >= total4) return;
    int j4  = (idx % (NN / 4)) * 4;
    int lag = (idx / (NN / 4)) % NLAG;
    int b   = idx / ((NN / 4) * NLAG);
    int jm  = j4 % 200;

    int r = lag * NB + b;
    float4 o4 = *reinterpret_cast<const float4*>(&g_C[(size_t)r * NN + j4]);
    float4 a4 = *reinterpret_cast<const float4*>(&g_C[(size_t)(384 + r) * NN + j4]);
    float4 n4 = *reinterpret_cast<const float4*>(&g_C[(size_t)(768 + r) * NN + j4]);
    float4 lam = *reinterpret_cast<const float4*>(&lambd[lag * 200 + jm]);
    float4 lv  = *reinterpret_cast<const float4*>(&l[lag * 200 + jm]);

    float ib = 1.f / g_belta[lag];
    float pf = g_pf[lag];
    float c2 = g_c2[lag];

    float4 o;
    o.x = lam.x * ib * (pf * o4.x + 3.f * lv.x * (a4.x + c2 * n4.x));
    o.y = lam.y * ib * (pf * o4.y + 3.f * lv.y * (a4.y + c2 * n4.y));
    o.z = lam.z * ib * (pf * o4.z + 3.f * lv.z * (a4.z + c2 * n4.z));
    o.w = lam.w * ib * (pf * o4.w + 3.f * lv.w * (a4.w + c2 * n4.w));
    *reinterpret_cast<float4*>(&out[(size_t)idx * 4]) = o;
}

// ---------------------------------------------------------------------------
extern "C" void kernel_launch(void* const* d_in, const int* in_sizes, int n_in,
                              void* d_out, int out_size) {
    const float* A          = (const float*)d_in[0];
    const float* WW         = (const float*)d_in[1];
    const float* train_init = (const float*)d_in[2];
    const float* alpha      = (const float*)d_in[3];
    const float* fract      = (const float*)d_in[4];
    const float* lambd      = (const float*)d_in[5];
    const float* l          = (const float*)d_in[6];
    float* out = (float*)d_out;

    cudaFuncSetAttribute(gemm_mma_kernel,
                         cudaFuncAttributeMaxDynamicSharedMemorySize,
                         2 * STAGE);

    prep_kernel<<<(PREP_TOTAL + 255) / 256, 256>>>(A, WW, train_init, alpha, fract);

    dim3 ggrid(NN / 80, MROWS / 64);              // (15, 18) = 270 CTAs
    gemm_mma_kernel<<<ggrid, 256, 2 * STAGE>>>();

    const int total4 = NB * NLAG * (NN / 4);
    epilogue_kernel<<<(total4 + 255) / 256, 256>>>(lambd, l, out);
}

// round 10
// speedup vs baseline: 2.3207x; 1.4065x over previous
#include <cuda_runtime.h>
#include <cuda_fp16.h>
#include <math_constants.h>
#include <cstdint>

// Problem constants
#define NLAG   12
#define NB     32
#define NN     1200
#define MROWS  1152          // 3 * NLAG * NB
#define KDIM   1200
#define KP     1216          // K padded to 38*32
#define NP     1280          // B storage width (padded)

// GEMM tiling: CTA 64m x 80n, BK=32, 256 threads (8 warps = 4m x 2n, 16x40)
#define BK      32
#define NCHUNK  (KP / BK)    // 38
#define AROWB   80
#define BROWB   176
#define A_TILE  (64 * AROWB)     // 5120
#define B_TILE  (32 * BROWB)     // 5632
#define OFF_A0  0
#define OFF_B0  A_TILE
#define STAGE   (A_TILE + B_TILE)   // 10752
#define NUNITS  576          // 16B units per chunk: B 320 + A 256

// Scratch (device globals; no allocation allowed)
__device__ __align__(16) __half g_A0[MROWS * KP];
__device__ __align__(16) __half g_B0[KP * NP];    // k-major
__device__ __align__(16) float g_C[MROWS * NN];
__device__ float g_belta[NLAG];
__device__ float g_c2[NLAG];
__device__ float g_pf[NLAG];

// ---------------------------------------------------------------------------
__device__ __forceinline__ uint32_t smem_u32(const void* p) {
    uint32_t a;
    asm("{ .reg .u64 t; cvta.to.shared.u64 t, %1; cvt.u32.u64 %0, t; }"
        : "=r"(a) : "l"(p));
    return a;
}

#define LDSM4(r, addr)                                                      \
    asm volatile("ldmatrix.sync.aligned.m8n8.x4.shared.b16 "                \
                 "{%0, %1, %2, %3}, [%4];"                                  \
                 : "=r"((r)[0]), "=r"((r)[1]), "=r"((r)[2]), "=r"((r)[3])   \
                 : "r"(addr))
#define LDSM4T(r, addr)                                                     \
    asm volatile("ldmatrix.sync.aligned.m8n8.x4.trans.shared.b16 "          \
                 "{%0, %1, %2, %3}, [%4];"                                  \
                 : "=r"((r)[0]), "=r"((r)[1]), "=r"((r)[2]), "=r"((r)[3])   \
                 : "r"(addr))
#define LDSM2T(r, addr)                                                     \
    asm volatile("ldmatrix.sync.aligned.m8n8.x2.trans.shared.b16 "          \
                 "{%0, %1}, [%2];"                                          \
                 : "=r"((r)[0]), "=r"((r)[1]) : "r"(addr))

#define MMA_F16(c, a, bb0, bb1)                                             \
    asm volatile("mma.sync.aligned.m16n8k16.row.col.f32.f16.f16.f32 "       \
                 "{%0, %1, %2, %3}, {%4, %5, %6, %7}, {%8, %9}, "           \
                 "{%0, %1, %2, %3};"                                        \
                 : "+f"((c)[0]), "+f"((c)[1]), "+f"((c)[2]), "+f"((c)[3])   \
                 : "r"((a)[0]), "r"((a)[1]), "r"((a)[2]), "r"((a)[3]),      \
                   "r"(bb0), "r"(bb1))

#define CP_ASYNC16(dst, src)                                                \
    asm volatile("cp.async.cg.shared.global [%0], [%1], 16;"                \
                 :: "r"(dst), "l"(__cvta_generic_to_global(src)))
#define CP_COMMIT() asm volatile("cp.async.commit_group;" ::: "memory")
#define CP_WAIT1()  asm volatile("cp.async.wait_group 1;" ::: "memory")
#define CP_WAIT0()  asm volatile("cp.async.wait_group 0;" ::: "memory")

// ---------------------------------------------------------------------------
__device__ __forceinline__ float gamma_fn(float x) {
    if (x > 0.f) return expf(lgammaf(x));
    return CUDART_PI_F / (sinf(CUDART_PI_F * x) * expf(lgammaf(1.f - x)));
}

// ---------------------------------------------------------------------------
// Fused prep. A rows: [0,384) A slice, [384,768) A_0_NEW, [768,1152) A_N_OLD.
//  [0, R0)   : A slice fp16 copy, 2 elems/thread (half2 store)
//  [R0,+R1)  : train_init gather, one thread per (b,i), coalesced read
//  [..,+R2)  : zero-fill k padding for rows [384,1152), half2
//  [..,+R3)  : B pack (k-major fp16, half2)
// ---------------------------------------------------------------------------
#define R0 (384 * KP / 2)
#define R1 (NB * NN)
#define R2 (768 * (KP - KDIM) / 2)
#define R3 (KP * (NP / 2))
#define PREP_TOTAL (R0 + R1 + R2 + R3)

__global__ void prep_kernel(const float* __restrict__ A,
                            const float* __restrict__ WW,
                            const float* __restrict__ train_init,
                            const float* __restrict__ alpha,
                            const float* __restrict__ fract) {
    int idx = blockIdx.x * blockDim.x + threadIdx.x;

    if (blockIdx.x == 0 && threadIdx.x < NLAG) {
        int lag = threadIdx.x;
        float a   = alpha[lag];
        float f   = fract[lag];
        float ga1 = gamma_fn(a + 1.f);
        float gm2 = gamma_fn(a - 2.f);
        float belta = 1.f
                    + ga1 / gamma_fn(a)
                    + ga1 / (2.f * gamma_fn(a - 1.f))
                    + ga1 / (6.f * gm2);
        g_belta[lag] = belta;
        g_c2[lag]    = ga1 / (6.f * gm2);
        g_pf[lag]    = 2.f * powf(3.f, f);
    }

    if (idx < R0) {
        int r = idx / (KP / 2);
        int k = (idx - r * (KP / 2)) * 2;      // KDIM even: pairs never straddle
        float2 v = make_float2(0.f, 0.f);
        if (k < KDIM)
            v = *reinterpret_cast<const float2*>(&A[r * KDIM + k]);
        reinterpret_cast<__half2*>(g_A0)[idx] =
            __halves2half2(__float2half(v.x), __float2half(v.y));
    } else if (idx < R0 + R1) {
        int p = idx - R0;
        int b = p / NN;
        int i = p - b * NN;
        const float2* ti = reinterpret_cast<const float2*>(
            train_init + (size_t)(b * NN + i) * 26);
#pragma unroll
        for (int j = 0; j < 13; j++) {
            __half h = __float2half(ti[j].y);
            if (j >= 1) {               // A_0_NEW: lag = j-1
                int row = 384 + (j - 1) * NB + b;
                g_A0[(size_t)row * KP + i] = h;
            }
            if (j <= 11) {              // A_N_OLD: lag = j
                int row = 768 + j * NB + b;
                g_A0[(size_t)row * KP + i] = h;
            }
        }
    } else if (idx < R0 + R1 + R2) {
        int p = idx - R0 - R1;
        int padw = (KP - KDIM) / 2;            // half2 pads per row
        int row = 384 + p / padw;
        int k   = KDIM + (p % padw) * 2;
        reinterpret_cast<__half2*>(&g_A0[(size_t)row * KP + k])[0] =
            __halves2half2(__float2half(0.f), __float2half(0.f));
    } else if (idx < PREP_TOTAL) {
        int p = idx - R0 - R1 - R2;
        int k = p / (NP / 2);
        int n = (p - k * (NP / 2)) * 2;
        float2 v = make_float2(0.f, 0.f);
        if (k < KDIM && n + 1 < NN)
            v = *reinterpret_cast<const float2*>(&WW[k * NN + n]);
        else if (k < KDIM && n < NN)
            v.x = WW[k * NN + n];
        reinterpret_cast<__half2*>(g_B0)[p] =
            __halves2half2(__float2half(v.x), __float2half(v.y));
    }
}

// ---------------------------------------------------------------------------
// cp.async issue for one chunk: B0 32x160B (320 units); A0 64x64B (256 units)
// ---------------------------------------------------------------------------
__device__ __forceinline__ void issue_chunk(uint32_t stage, int m0, int n0,
                                            int k0, int tid) {
#pragma unroll
    for (int i = 0; i < 3; i++) {
        int u = tid + i * 256;
        if (u < NUNITS) {
            uint32_t dst;
            const __half* src;
            if (u < 320) {                  // B tile
                int row = u / 10;
                int seg = u - row * 10;
                src = g_B0 + (size_t)(k0 + row) * NP + n0 + seg * 8;
                dst = stage + OFF_B0 + row * BROWB + seg * 16;
            } else {                        // A tile
                int v   = u - 320;
                int row = v >> 2;
                int seg = v & 3;
                src = g_A0 + (size_t)(m0 + row) * KP + k0 + seg * 8;
                dst = stage + OFF_A0 + row * AROWB + seg * 16;
            }
            CP_ASYNC16(dst, src);
        }
    }
}

// ---------------------------------------------------------------------------
// Pure fp16 HMMA GEMM: g_C = tanh(-(X @ WW)).
// CTA 64x80, 8 warps (16m x 40n each), BK=32 double-buffered.
// Grid (15, 18) = 270 CTAs.
// ---------------------------------------------------------------------------
__global__ __launch_bounds__(256, 3)
void gemm_mma_kernel() {
    extern __shared__ __align__(16) char smem[];
    const uint32_t sb = smem_u32(smem);
    const int tid  = threadIdx.x;
    const int lane = tid & 31;
    const int wid  = tid >> 5;
    const int wm   = wid & 3;
    const int wn   = wid >> 2;
    const int m0   = blockIdx.y * 64;
    const int n0   = blockIdx.x * 80;

    const int j = lane >> 3, rr = lane & 7;
    const uint32_t a_off  = (uint32_t)((wm * 16 + (j & 1) * 8 + rr) * AROWB + (j >> 1) * 16);
    const uint32_t b4_off = (uint32_t)(((j & 1) * 8 + rr) * BROWB + (j >> 1) * 16 + wn * 80);
    const uint32_t b2_off = (uint32_t)(((j & 1) * 8 + rr) * BROWB + wn * 80 + 64);

    float acc[5][4];
#pragma unroll
    for (int f = 0; f < 5; f++)
#pragma unroll
        for (int e = 0; e < 4; e++) acc[f][e] = 0.f;

    issue_chunk(sb, m0, n0, 0, tid);
    CP_COMMIT();

    for (int c = 0; c < NCHUNK; c++) {
        const uint32_t stage = sb + (uint32_t)(c & 1) * STAGE;
        if (c + 1 < NCHUNK) {
            issue_chunk(sb + (uint32_t)((c + 1) & 1) * STAGE, m0, n0,
                        (c + 1) * BK, tid);
            CP_COMMIT();
            CP_WAIT1();
        } else {
            CP_WAIT0();
        }
        __syncthreads();

#pragma unroll
        for (int ks = 0; ks < 2; ks++) {
            uint32_t A0f[4];
            LDSM4(A0f, stage + OFF_A0 + a_off + ks * 32);
            uint32_t B0r[10];
            LDSM4T(&B0r[0], stage + OFF_B0 + b4_off + ks * 16 * BROWB);
            LDSM4T(&B0r[4], stage + OFF_B0 + b4_off + 32 + ks * 16 * BROWB);
            LDSM2T(&B0r[8], stage + OFF_B0 + b2_off + ks * 16 * BROWB);
#pragma unroll
            for (int f = 0; f < 5; f++)
                MMA_F16(acc[f], A0f, B0r[2 * f], B0r[2 * f + 1]);
        }
        __syncthreads();
    }

    // Store with fused tanh(-x); cols always < 1200 (grid.x*80 == NN).
    const int gid = lane >> 2, tig = lane & 3;
    const int row = m0 + wm * 16 + gid;
    float* c0p = &g_C[(size_t)row * NN];
    float* c1p = &g_C[(size_t)(row + 8) * NN];
#pragma unroll
    for (int f = 0; f < 5; f++) {
        int col = n0 + wn * 40 + f * 8 + tig * 2;
        float2 lo, hi;
        lo.x = tanhf(-acc[f][0]);
        lo.y = tanhf(-acc[f][1]);
        hi.x = tanhf(-acc[f][2]);
        hi.y = tanhf(-acc[f][3]);
        *reinterpret_cast<float2*>(c0p + col) = lo;
        *reinterpret_cast<float2*>(c1p + col) = hi;
    }
}

// ---------------------------------------------------------------------------
// Final combine (float4): out = lambd/belta * ( pf*OUT + 3*l*(A0NEW + c2*ANOLD) )
// ---------------------------------------------------------------------------
__global__ void epilogue_kernel(const float* __restrict__ lambd,
                                const float* __restrict__ l,
                                float* __restrict__ out) {
    int idx = blockIdx.x * blockDim.x + threadIdx.x;
    const int total4 = NB * NLAG * (NN / 4);
    if (idx >= total4) return;
    int j4  = (idx % (NN / 4)) * 4;
    int lag = (idx / (NN / 4)) % NLAG;
    int b   = idx / ((NN / 4) * NLAG);
    int jm  = j4 % 200;

    int r = lag * NB + b;
    float4 o4 = *reinterpret_cast<const float4*>(&g_C[(size_t)r * NN + j4]);
    float4 a4 = *reinterpret_cast<const float4*>(&g_C[(size_t)(384 + r) * NN + j4]);
    float4 n4 = *reinterpret_cast<const float4*>(&g_C[(size_t)(768 + r) * NN + j4]);
    float4 lam = *reinterpret_cast<const float4*>(&lambd[lag * 200 + jm]);
    float4 lv  = *reinterpret_cast<const float4*>(&l[lag * 200 + jm]);

    float ib = 1.f / g_belta[lag];
    float pf = g_pf[lag];
    float c2 = g_c2[lag];

    float4 o;
    o.x = lam.x * ib * (pf * o4.x + 3.f * lv.x * (a4.x + c2 * n4.x));
    o.y = lam.y * ib * (pf * o4.y + 3.f * lv.y * (a4.y + c2 * n4.y));
    o.z = lam.z * ib * (pf * o4.z + 3.f * lv.z * (a4.z + c2 * n4.z));
    o.w = lam.w * ib * (pf * o4.w + 3.f * lv.w * (a4.w + c2 * n4.w));
    *reinterpret_cast<float4*>(&out[(size_t)idx * 4]) = o;
}

// ---------------------------------------------------------------------------
extern "C" void kernel_launch(void* const* d_in, const int* in_sizes, int n_in,
                              void* d_out, int out_size) {
    const float* A          = (const float*)d_in[0];
    const float* WW         = (const float*)d_in[1];
    const float* train_init = (const float*)d_in[2];
    const float* alpha      = (const float*)d_in[3];
    const float* fract      = (const float*)d_in[4];
    const float* lambd      = (const float*)d_in[5];
    const float* l          = (const float*)d_in[6];
    float* out = (float*)d_out;

    cudaFuncSetAttribute(gemm_mma_kernel,
                         cudaFuncAttributeMaxDynamicSharedMemorySize,
                         2 * STAGE);

    prep_kernel<<<(PREP_TOTAL + 255) / 256, 256>>>(A, WW, train_init, alpha, fract);

    dim3 ggrid(NN / 80, MROWS / 64);              // (15, 18) = 270 CTAs
    gemm_mma_kernel<<<ggrid, 256, 2 * STAGE>>>();

    const int total4 = NB * NLAG * (NN / 4);
    epilogue_kernel<<<(total4 + 255) / 256, 256>>>(lambd, l, out);
}

// round 11
// speedup vs baseline: 2.3410x; 1.0088x over previous
#include <cuda_runtime.h>
#include <cuda_fp16.h>
#include <math_constants.h>
#include <cstdint>

// Problem constants
#define NLAG   12
#define NB     32
#define NN     1200
#define MROWS  1152          // 3 * NLAG * NB
#define KDIM   1200
#define KP     1216          // K padded to 19*64
#define NP     1280          // B storage width (padded)

// GEMM tiling: CTA 64m x 80n, BK=64, 256 threads (8 warps = 4m x 2n, 16x40)
#define BK      64
#define NCHUNK  (KP / BK)    // 19
#define AROWB   144          // A smem row pitch (64 fp16 = 128B + 16B pad)
#define BROWB   176          // B smem row pitch (80 fp16 = 160B + 16B pad)
#define A_TILE  (64 * AROWB)     // 9216
#define B_TILE  (64 * BROWB)     // 11264
#define OFF_A0  0
#define OFF_B0  A_TILE
#define STAGE   (A_TILE + B_TILE)   // 20480
#define NUNITS  1152         // 16B units per chunk: B 640 + A 512

// Scratch (device globals; no allocation allowed)
__device__ __align__(16) __half g_A0[MROWS * KP];
__device__ __align__(16) __half g_B0[KP * NP];    // k-major
__device__ __align__(16) float g_C[MROWS * NN];
__device__ float g_belta[NLAG];
__device__ float g_c2[NLAG];
__device__ float g_pf[NLAG];

// ---------------------------------------------------------------------------
__device__ __forceinline__ uint32_t smem_u32(const void* p) {
    uint32_t a;
    asm("{ .reg .u64 t; cvta.to.shared.u64 t, %1; cvt.u32.u64 %0, t; }"
        : "=r"(a) : "l"(p));
    return a;
}

#define LDSM4(r, addr)                                                      \
    asm volatile("ldmatrix.sync.aligned.m8n8.x4.shared.b16 "                \
                 "{%0, %1, %2, %3}, [%4];"                                  \
                 : "=r"((r)[0]), "=r"((r)[1]), "=r"((r)[2]), "=r"((r)[3])   \
                 : "r"(addr))
#define LDSM4T(r, addr)                                                     \
    asm volatile("ldmatrix.sync.aligned.m8n8.x4.trans.shared.b16 "          \
                 "{%0, %1, %2, %3}, [%4];"                                  \
                 : "=r"((r)[0]), "=r"((r)[1]), "=r"((r)[2]), "=r"((r)[3])   \
                 : "r"(addr))
#define LDSM2T(r, addr)                                                     \
    asm volatile("ldmatrix.sync.aligned.m8n8.x2.trans.shared.b16 "          \
                 "{%0, %1}, [%2];"                                          \
                 : "=r"((r)[0]), "=r"((r)[1]) : "r"(addr))

#define MMA_F16(c, a, bb0, bb1)                                             \
    asm volatile("mma.sync.aligned.m16n8k16.row.col.f32.f16.f16.f32 "       \
                 "{%0, %1, %2, %3}, {%4, %5, %6, %7}, {%8, %9}, "           \
                 "{%0, %1, %2, %3};"                                        \
                 : "+f"((c)[0]), "+f"((c)[1]), "+f"((c)[2]), "+f"((c)[3])   \
                 : "r"((a)[0]), "r"((a)[1]), "r"((a)[2]), "r"((a)[3]),      \
                   "r"(bb0), "r"(bb1))

#define CP_ASYNC16(dst, src)                                                \
    asm volatile("cp.async.cg.shared.global [%0], [%1], 16;"                \
                 :: "r"(dst), "l"(__cvta_generic_to_global(src)))
#define CP_COMMIT() asm volatile("cp.async.commit_group;" ::: "memory")
#define CP_WAIT1()  asm volatile("cp.async.wait_group 1;" ::: "memory")
#define CP_WAIT0()  asm volatile("cp.async.wait_group 0;" ::: "memory")

// ---------------------------------------------------------------------------
__device__ __forceinline__ float gamma_fn(float x) {
    if (x > 0.f) return expf(lgammaf(x));
    return CUDART_PI_F / (sinf(CUDART_PI_F * x) * expf(lgammaf(1.f - x)));
}

__device__ __forceinline__ uint32_t pack4h(float a, float b, float c, float d,
                                           uint32_t& hi) {
    __half2 lo2 = __halves2half2(__float2half(a), __float2half(b));
    __half2 hi2 = __halves2half2(__float2half(c), __float2half(d));
    hi = *reinterpret_cast<uint32_t*>(&hi2);
    return *reinterpret_cast<uint32_t*>(&lo2);
}

// ---------------------------------------------------------------------------
// Fused prep (vectorized). A rows: [0,384) A slice, [384,768) A_0_NEW,
// [768,1152) A_N_OLD.
//  [0, R0)   : A slice, 4 floats/thread -> 4 fp16 (8B store)
//  [R0,+R1)  : train_init, one thread per (b, i-pair): 13 float4 contiguous
//              read, half2 writes into 24 rows
//  [..,+R2)  : zero-fill k padding rows [384,1152), 8B stores
//  [..,+R3)  : B pack, 4 floats/thread (8B store)
// ---------------------------------------------------------------------------
#define R0 (384 * KP / 4)
#define R1 (NB * NN / 2)
#define R2 (768 * (KP - KDIM) / 4)
#define R3 (KP * NP / 4)
#define PREP_TOTAL (R0 + R1 + R2 + R3)

__global__ void prep_kernel(const float* __restrict__ A,
                            const float* __restrict__ WW,
                            const float* __restrict__ train_init,
                            const float* __restrict__ alpha,
                            const float* __restrict__ fract) {
    int idx = blockIdx.x * blockDim.x + threadIdx.x;

    if (blockIdx.x == 0 && threadIdx.x < NLAG) {
        int lag = threadIdx.x;
        float a   = alpha[lag];
        float f   = fract[lag];
        float ga1 = gamma_fn(a + 1.f);
        float gm2 = gamma_fn(a - 2.f);
        float belta = 1.f
                    + ga1 / gamma_fn(a)
                    + ga1 / (2.f * gamma_fn(a - 1.f))
                    + ga1 / (6.f * gm2);
        g_belta[lag] = belta;
        g_c2[lag]    = ga1 / (6.f * gm2);
        g_pf[lag]    = 2.f * powf(3.f, f);
    }

    if (idx < R0) {
        int r = idx / (KP / 4);
        int k = (idx - r * (KP / 4)) * 4;      // KDIM % 4 == 0: no straddle
        float4 v = make_float4(0.f, 0.f, 0.f, 0.f);
        if (k < KDIM)
            v = *reinterpret_cast<const float4*>(&A[r * KDIM + k]);
        uint32_t hi, lo = pack4h(v.x, v.y, v.z, v.w, hi);
        reinterpret_cast<uint2*>(g_A0)[idx] = make_uint2(lo, hi);
    } else if (idx < R0 + R1) {
        int p = idx - R0;
        int b = p / (NN / 2);
        int i = (p - b * (NN / 2)) * 2;        // even i
        const float4* ti4 = reinterpret_cast<const float4*>(
            train_init + (size_t)(b * NN + i) * 26);
        float buf[52];
#pragma unroll
        for (int q = 0; q < 13; q++) {
            float4 v = ti4[q];
            buf[q * 4 + 0] = v.x; buf[q * 4 + 1] = v.y;
            buf[q * 4 + 2] = v.z; buf[q * 4 + 3] = v.w;
        }
#pragma unroll
        for (int j = 0; j < 13; j++) {
            __half2 h = __halves2half2(__float2half(buf[2 * j + 1]),
                                       __float2half(buf[26 + 2 * j + 1]));
            if (j >= 1) {               // A_0_NEW: lag = j-1
                int row = 384 + (j - 1) * NB + b;
                *reinterpret_cast<__half2*>(&g_A0[(size_t)row * KP + i]) = h;
            }
            if (j <= 11) {              // A_N_OLD: lag = j
                int row = 768 + j * NB + b;
                *reinterpret_cast<__half2*>(&g_A0[(size_t)row * KP + i]) = h;
            }
        }
    } else if (idx < R0 + R1 + R2) {
        int p = idx - R0 - R1;
        int padw = (KP - KDIM) / 4;            // 4-elem pads per row
        int row = 384 + p / padw;
        int k   = KDIM + (p % padw) * 4;
        reinterpret_cast<uint2*>(&g_A0[(size_t)row * KP + k])[0] = make_uint2(0u, 0u);
    } else if (idx < PREP_TOTAL) {
        int p = idx - R0 - R1 - R2;
        int k = p / (NP / 4);
        int n = (p - k * (NP / 4)) * 4;        // NN % 4 == 0: no straddle
        float4 v = make_float4(0.f, 0.f, 0.f, 0.f);
        if (k < KDIM && n < NN)
            v = *reinterpret_cast<const float4*>(&WW[k * NN + n]);
        uint32_t hi, lo = pack4h(v.x, v.y, v.z, v.w, hi);
        reinterpret_cast<uint2*>(g_B0)[p] = make_uint2(lo, hi);
    }
}

// ---------------------------------------------------------------------------
// cp.async issue for one chunk: B 64x160B (640 units); A 64x128B (512 units)
// ---------------------------------------------------------------------------
__device__ __forceinline__ void issue_chunk(uint32_t stage, int m0, int n0,
                                            int k0, int tid) {
#pragma unroll
    for (int i = 0; i < 5; i++) {
        int u = tid + i * 256;
        if (u < NUNITS) {
            uint32_t dst;
            const __half* src;
            if (u < 640) {                  // B tile: 64 rows x 10 segs
                int row = u / 10;
                int seg = u - row * 10;
                src = g_B0 + (size_t)(k0 + row) * NP + n0 + seg * 8;
                dst = stage + OFF_B0 + row * BROWB + seg * 16;
            } else {                        // A tile: 64 rows x 8 segs
                int v   = u - 640;
                int row = v >> 3;
                int seg = v & 7;
                src = g_A0 + (size_t)(m0 + row) * KP + k0 + seg * 8;
                dst = stage + OFF_A0 + row * AROWB + seg * 16;
            }
            CP_ASYNC16(dst, src);
        }
    }
}

// ---------------------------------------------------------------------------
// Pure fp16 HMMA GEMM: g_C = tanh(-(X @ WW)).
// CTA 64x80, 8 warps (16m x 40n each), BK=64 double-buffered.
// Grid (15, 18) = 270 CTAs.
// ---------------------------------------------------------------------------
__global__ __launch_bounds__(256, 3)
void gemm_mma_kernel() {
    extern __shared__ __align__(16) char smem[];
    const uint32_t sb = smem_u32(smem);
    const int tid  = threadIdx.x;
    const int lane = tid & 31;
    const int wid  = tid >> 5;
    const int wm   = wid & 3;
    const int wn   = wid >> 2;
    const int m0   = blockIdx.y * 64;
    const int n0   = blockIdx.x * 80;

    const int j = lane >> 3, rr = lane & 7;
    const uint32_t a_off  = (uint32_t)((wm * 16 + (j & 1) * 8 + rr) * AROWB + (j >> 1) * 16);
    const uint32_t b4_off = (uint32_t)(((j & 1) * 8 + rr) * BROWB + (j >> 1) * 16 + wn * 80);
    const uint32_t b2_off = (uint32_t)(((j & 1) * 8 + rr) * BROWB + wn * 80 + 64);

    float acc[5][4];
#pragma unroll
    for (int f = 0; f < 5; f++)
#pragma unroll
        for (int e = 0; e < 4; e++) acc[f][e] = 0.f;

    issue_chunk(sb, m0, n0, 0, tid);
    CP_COMMIT();

    for (int c = 0; c < NCHUNK; c++) {
        const uint32_t stage = sb + (uint32_t)(c & 1) * STAGE;
        if (c + 1 < NCHUNK) {
            issue_chunk(sb + (uint32_t)((c + 1) & 1) * STAGE, m0, n0,
                        (c + 1) * BK, tid);
            CP_COMMIT();
            CP_WAIT1();
        } else {
            CP_WAIT0();
        }
        __syncthreads();

#pragma unroll
        for (int ks = 0; ks < 4; ks++) {
            uint32_t A0f[4];
            LDSM4(A0f, stage + OFF_A0 + a_off + ks * 32);
            uint32_t B0r[10];
            LDSM4T(&B0r[0], stage + OFF_B0 + b4_off + ks * 16 * BROWB);
            LDSM4T(&B0r[4], stage + OFF_B0 + b4_off + 32 + ks * 16 * BROWB);
            LDSM2T(&B0r[8], stage + OFF_B0 + b2_off + ks * 16 * BROWB);
#pragma unroll
            for (int f = 0; f < 5; f++)
                MMA_F16(acc[f], A0f, B0r[2 * f], B0r[2 * f + 1]);
        }
        __syncthreads();
    }

    // Store with fused tanh(-x); cols always < 1200 (grid.x*80 == NN).
    const int gid = lane >> 2, tig = lane & 3;
    const int row = m0 + wm * 16 + gid;
    float* c0p = &g_C[(size_t)row * NN];
    float* c1p = &g_C[(size_t)(row + 8) * NN];
#pragma unroll
    for (int f = 0; f < 5; f++) {
        int col = n0 + wn * 40 + f * 8 + tig * 2;
        float2 lo, hi;
        lo.x = tanhf(-acc[f][0]);
        lo.y = tanhf(-acc[f][1]);
        hi.x = tanhf(-acc[f][2]);
        hi.y = tanhf(-acc[f][3]);
        *reinterpret_cast<float2*>(c0p + col) = lo;
        *reinterpret_cast<float2*>(c1p + col) = hi;
    }
}

// ---------------------------------------------------------------------------
// Final combine (float4): out = lambd/belta * ( pf*OUT + 3*l*(A0NEW + c2*ANOLD) )
// ---------------------------------------------------------------------------
__global__ void epilogue_kernel(const float* __restrict__ lambd,
                                const float* __restrict__ l,
                                float* __restrict__ out) {
    int idx = blockIdx.x * blockDim.x + threadIdx.x;
    const int total4 = NB * NLAG * (NN / 4);
    if (idx >= total4) return;
    int j4  = (idx % (NN / 4)) * 4;
    int lag = (idx / (NN / 4)) % NLAG;
    int b   = idx / ((NN / 4) * NLAG);
    int jm  = j4 % 200;

    int r = lag * NB + b;
    float4 o4 = *reinterpret_cast<const float4*>(&g_C[(size_t)r * NN + j4]);
    float4 a4 = *reinterpret_cast<const float4*>(&g_C[(size_t)(384 + r) * NN + j4]);
    float4 n4 = *reinterpret_cast<const float4*>(&g_C[(size_t)(768 + r) * NN + j4]);
    float4 lam = *reinterpret_cast<const float4*>(&lambd[lag * 200 + jm]);
    float4 lv  = *reinterpret_cast<const float4*>(&l[lag * 200 + jm]);

    float ib = 1.f / g_belta[lag];
    float pf = g_pf[lag];
    float c2 = g_c2[lag];

    float4 o;
    o.x = lam.x * ib * (pf * o4.x + 3.f * lv.x * (a4.x + c2 * n4.x));
    o.y = lam.y * ib * (pf * o4.y + 3.f * lv.y * (a4.y + c2 * n4.y));
    o.z = lam.z * ib * (pf * o4.z + 3.f * lv.z * (a4.z + c2 * n4.z));
    o.w = lam.w * ib * (pf * o4.w + 3.f * lv.w * (a4.w + c2 * n4.w));
    *reinterpret_cast<float4*>(&out[(size_t)idx * 4]) = o;
}

// ---------------------------------------------------------------------------
extern "C" void kernel_launch(void* const* d_in, const int* in_sizes, int n_in,
                              void* d_out, int out_size) {
    const float* A          = (const float*)d_in[0];
    const float* WW         = (const float*)d_in[1];
    const float* train_init = (const float*)d_in[2];
    const float* alpha      = (const float*)d_in[3];
    const float* fract      = (const float*)d_in[4];
    const float* lambd      = (const float*)d_in[5];
    const float* l          = (const float*)d_in[6];
    float* out = (float*)d_out;

    cudaFuncSetAttribute(gemm_mma_kernel,
                         cudaFuncAttributeMaxDynamicSharedMemorySize,
                         2 * STAGE);

    prep_kernel<<<(PREP_TOTAL + 255) / 256, 256>>>(A, WW, train_init, alpha, fract);

    dim3 ggrid(NN / 80, MROWS / 64);              // (15, 18) = 270 CTAs
    gemm_mma_kernel<<<ggrid, 256, 2 * STAGE>>>();

    const int total4 = NB * NLAG * (NN / 4);
    epilogue_kernel<<<(total4 + 255) / 256, 256>>>(lambd, l, out);
}